// round 2
// baseline (speedup 1.0000x reference)
#include <cuda_runtime.h>
#include <cuda_bf16.h>
#include <math.h>

// Problem constants
#define Bsz 8
#define Lsz 2048
#define Dsz 768
#define Hsz 512

#define INV_SQRT_L 0.022097086912079608f   // 1/sqrt(2048)
#define INV_SQRT_D 0.036084391824351615f   // 1/sqrt(768)
#define INV_L      4.8828125e-4f           // 1/2048

// ---------------------------------------------------------------------------
// Scratch (static device globals; no allocation anywhere)
// ---------------------------------------------------------------------------
__device__ float d_S[(size_t)Bsz * Lsz * Lsz];      // 134 MB scores
__device__ float d_h[(size_t)Bsz * Lsz * Hsz];      // 32 MB hidden tanh(v@W1+b1)
__device__ float d_g[Bsz * Lsz];                    // gate
__device__ float d_cm[Bsz * Lsz];                   // column max
__device__ float d_alpha[Bsz * Lsz];                // (1-g)/(colsum*sqrt(D))
__device__ float d_beta[Bsz * Lsz];                 // g/(L*sqrt(D))

// ---------------------------------------------------------------------------
// Tiled SGEMM parameters: 128x128 block tile, 16 K-tile, 8x8 per-thread,
// 256 threads/block, register-prefetch double buffering.
// ---------------------------------------------------------------------------
#define BM 128
#define BN 128
#define BK 16
#define TM 8
#define TN 8

// ===========================================================================
// Kernel 1: h = tanh(Vflat @ W1 + b1)      (NN, M=16384, N=512, K=768)
// ===========================================================================
__global__ void __launch_bounds__(256)
gemm_h_kernel(const float* __restrict__ V, const float* __restrict__ W1,
              const float* __restrict__ b1) {
    __shared__ float As[BK][BM];
    __shared__ float Bs[BK][BN];

    const int lda = Dsz, ldb = Hsz, ldc = Hsz;
    const int tid = threadIdx.x;
    const int tx = tid & 15, ty = tid >> 4;
    const int m0 = blockIdx.y * BM;
    const int n0 = blockIdx.x * BN;

    // Per-thread load coordinates (2 float4 for A, 2 float4 for B per tile)
    int aRow[2], aC4[2], bKr[2], bC4[2];
    #pragma unroll
    for (int t = 0; t < 2; t++) {
        int i = tid + t * 256;
        aRow[t] = i >> 2;        aC4[t] = (i & 3) * 4;
        bKr[t]  = i >> 5;        bC4[t] = (i & 31) * 4;
    }

    float acc[TM][TN];
    #pragma unroll
    for (int i = 0; i < TM; i++)
        #pragma unroll
        for (int j = 0; j < TN; j++) acc[i][j] = 0.f;

    // Preload first tile
    float4 pa[2], pb[2];
    #pragma unroll
    for (int t = 0; t < 2; t++) {
        pa[t] = *reinterpret_cast<const float4*>(&V[(size_t)(m0 + aRow[t]) * lda + aC4[t]]);
        pb[t] = *reinterpret_cast<const float4*>(&W1[(size_t)bKr[t] * ldb + n0 + bC4[t]]);
    }

    for (int k0 = 0; k0 < Dsz; k0 += BK) {
        // Commit prefetched tile to smem
        #pragma unroll
        for (int t = 0; t < 2; t++) {
            As[aC4[t] + 0][aRow[t]] = pa[t].x; As[aC4[t] + 1][aRow[t]] = pa[t].y;
            As[aC4[t] + 2][aRow[t]] = pa[t].z; As[aC4[t] + 3][aRow[t]] = pa[t].w;
            *reinterpret_cast<float4*>(&Bs[bKr[t]][bC4[t]]) = pb[t];
        }
        __syncthreads();

        // Prefetch next tile into registers
        if (k0 + BK < Dsz) {
            #pragma unroll
            for (int t = 0; t < 2; t++) {
                pa[t] = *reinterpret_cast<const float4*>(
                    &V[(size_t)(m0 + aRow[t]) * lda + (k0 + BK) + aC4[t]]);
                pb[t] = *reinterpret_cast<const float4*>(
                    &W1[(size_t)(k0 + BK + bKr[t]) * ldb + n0 + bC4[t]]);
            }
        }

        #pragma unroll
        for (int k = 0; k < BK; k++) {
            float a[TM], b[TN];
            #pragma unroll
            for (int i = 0; i < TM; i++) a[i] = As[k][ty * TM + i];
            #pragma unroll
            for (int j = 0; j < TN; j++) b[j] = Bs[k][tx * TN + j];
            #pragma unroll
            for (int i = 0; i < TM; i++)
                #pragma unroll
                for (int j = 0; j < TN; j++) acc[i][j] = fmaf(a[i], b[j], acc[i][j]);
        }
        __syncthreads();
    }

    #pragma unroll
    for (int i = 0; i < TM; i++) {
        int m = m0 + ty * TM + i;
        #pragma unroll
        for (int j = 0; j < TN; j += 4) {
            int n = n0 + tx * TN + j;
            float4 v4;
            v4.x = tanhf(acc[i][j + 0] + b1[n + 0]);
            v4.y = tanhf(acc[i][j + 1] + b1[n + 1]);
            v4.z = tanhf(acc[i][j + 2] + b1[n + 2]);
            v4.w = tanhf(acc[i][j + 3] + b1[n + 3]);
            *reinterpret_cast<float4*>(&d_h[(size_t)m * ldc + n]) = v4;
        }
    }
}

// ===========================================================================
// Kernel 2: g[r] = h[r,:] . W2 + b2        (one warp per row)
// ===========================================================================
__global__ void __launch_bounds__(256)
reduce_g_kernel(const float* __restrict__ W2, const float* __restrict__ b2) {
    int warp = threadIdx.x >> 5, lane = threadIdx.x & 31;
    int row = blockIdx.x * 8 + warp;
    const float* hr = &d_h[(size_t)row * Hsz];
    float s = 0.f;
    #pragma unroll 4
    for (int i = lane; i < Hsz; i += 32) s = fmaf(hr[i], W2[i], s);
    #pragma unroll
    for (int off = 16; off; off >>= 1) s += __shfl_xor_sync(0xFFFFFFFFu, s, off);
    if (lane == 0) d_g[row] = s + b2[0];
}

// ===========================================================================
// Kernel 3: S = Q @ K^T * (1/sqrt(L))      (NT, per batch 2048x2048x768)
// ===========================================================================
__global__ void __launch_bounds__(256)
gemm_S_kernel(const float* __restrict__ Q, const float* __restrict__ Kmat) {
    __shared__ float As[BK][BM];
    __shared__ float Bs[BK][BN];

    const int b = blockIdx.z;
    const float* A  = Q    + (size_t)b * Lsz * Dsz;
    const float* Bm = Kmat + (size_t)b * Lsz * Dsz;
    float* C = &d_S[(size_t)b * Lsz * Lsz];
    const int lda = Dsz, ldb = Dsz, ldc = Lsz;

    const int tid = threadIdx.x;
    const int tx = tid & 15, ty = tid >> 4;
    const int m0 = blockIdx.y * BM;
    const int n0 = blockIdx.x * BN;

    int aRow[2], aC4[2];
    #pragma unroll
    for (int t = 0; t < 2; t++) {
        int i = tid + t * 256;
        aRow[t] = i >> 2; aC4[t] = (i & 3) * 4;
    }

    float acc[TM][TN];
    #pragma unroll
    for (int i = 0; i < TM; i++)
        #pragma unroll
        for (int j = 0; j < TN; j++) acc[i][j] = 0.f;

    float4 pa[2], pb[2];
    #pragma unroll
    for (int t = 0; t < 2; t++) {
        pa[t] = *reinterpret_cast<const float4*>(&A [(size_t)(m0 + aRow[t]) * lda + aC4[t]]);
        pb[t] = *reinterpret_cast<const float4*>(&Bm[(size_t)(n0 + aRow[t]) * ldb + aC4[t]]);
    }

    for (int k0 = 0; k0 < Dsz; k0 += BK) {
        #pragma unroll
        for (int t = 0; t < 2; t++) {
            As[aC4[t] + 0][aRow[t]] = pa[t].x; As[aC4[t] + 1][aRow[t]] = pa[t].y;
            As[aC4[t] + 2][aRow[t]] = pa[t].z; As[aC4[t] + 3][aRow[t]] = pa[t].w;
            Bs[aC4[t] + 0][aRow[t]] = pb[t].x; Bs[aC4[t] + 1][aRow[t]] = pb[t].y;
            Bs[aC4[t] + 2][aRow[t]] = pb[t].z; Bs[aC4[t] + 3][aRow[t]] = pb[t].w;
        }
        __syncthreads();

        if (k0 + BK < Dsz) {
            #pragma unroll
            for (int t = 0; t < 2; t++) {
                pa[t] = *reinterpret_cast<const float4*>(
                    &A [(size_t)(m0 + aRow[t]) * lda + (k0 + BK) + aC4[t]]);
                pb[t] = *reinterpret_cast<const float4*>(
                    &Bm[(size_t)(n0 + aRow[t]) * ldb + (k0 + BK) + aC4[t]]);
            }
        }

        #pragma unroll
        for (int k = 0; k < BK; k++) {
            float a[TM], bb[TN];
            #pragma unroll
            for (int i = 0; i < TM; i++) a[i] = As[k][ty * TM + i];
            #pragma unroll
            for (int j = 0; j < TN; j++) bb[j] = Bs[k][tx * TN + j];
            #pragma unroll
            for (int i = 0; i < TM; i++)
                #pragma unroll
                for (int j = 0; j < TN; j++) acc[i][j] = fmaf(a[i], bb[j], acc[i][j]);
        }
        __syncthreads();
    }

    #pragma unroll
    for (int i = 0; i < TM; i++) {
        int m = m0 + ty * TM + i;
        #pragma unroll
        for (int j = 0; j < TN; j += 4) {
            float4 v4;
            v4.x = acc[i][j + 0] * INV_SQRT_L;
            v4.y = acc[i][j + 1] * INV_SQRT_L;
            v4.z = acc[i][j + 2] * INV_SQRT_L;
            v4.w = acc[i][j + 3] * INV_SQRT_L;
            *reinterpret_cast<float4*>(&C[(size_t)m * ldc + n0 + tx * TN + j]) = v4;
        }
    }
}

// ===========================================================================
// Kernel 4: column stats (softmax over q axis) + per-k coefficients
//   cm[b,k]    = max_q S[b,q,k]
//   cs         = sum_q exp(S - cm)
//   alpha[b,k] = (1-g)/(cs*sqrt(D)),  beta[b,k] = g/(L*sqrt(D))
// Block: (32 k-lanes, 16 q-threads); grid: (L/32, B)
// ===========================================================================
__global__ void __launch_bounds__(512)
colstats_kernel() {
    const int b = blockIdx.y;
    const int kx = threadIdx.x;                 // 0..31
    const int qy = threadIdx.y;                 // 0..15
    const int k = blockIdx.x * 32 + kx;
    const float* Sb = &d_S[(size_t)b * Lsz * Lsz];

    __shared__ float red[16][33];

    float m = -INFINITY;
    #pragma unroll 4
    for (int q = qy; q < Lsz; q += 16)
        m = fmaxf(m, Sb[(size_t)q * Lsz + k]);
    red[qy][kx] = m;
    __syncthreads();
    if (qy == 0) {
        float mm = red[0][kx];
        #pragma unroll
        for (int i = 1; i < 16; i++) mm = fmaxf(mm, red[i][kx]);
        red[0][kx] = mm;
    }
    __syncthreads();
    m = red[0][kx];
    __syncthreads();

    float s = 0.f;
    #pragma unroll 4
    for (int q = qy; q < Lsz; q += 16)
        s += __expf(Sb[(size_t)q * Lsz + k] - m);
    red[qy][kx] = s;
    __syncthreads();
    if (qy == 0) {
        float ss = red[0][kx];
        #pragma unroll
        for (int i = 1; i < 16; i++) ss += red[i][kx];
        float gk = d_g[b * Lsz + k];
        d_cm[b * Lsz + k]    = m;
        d_alpha[b * Lsz + k] = (1.0f - gk) * INV_SQRT_D / ss;
        d_beta[b * Lsz + k]  = gk * INV_L * INV_SQRT_D;
    }
}

// ===========================================================================
// Kernel 5: row pass — W[b,q,k] = softmax_k( exp(S-cm[k])*alpha[k]+beta[k] )
// A is tiny (|A| < ~0.2) so no max subtraction needed. One block per row.
// ===========================================================================
__global__ void __launch_bounds__(256)
rowpass_kernel(float* __restrict__ Wout) {
    const int b = blockIdx.y;
    const int q = blockIdx.x;
    const float* Srow = &d_S[((size_t)b * Lsz + q) * Lsz];
    float* Wrow = Wout + ((size_t)b * Lsz + q) * Lsz;
    const float* cmb = &d_cm[b * Lsz];
    const float* alb = &d_alpha[b * Lsz];
    const float* beb = &d_beta[b * Lsz];
    const int t = threadIdx.x;

    float e[8];
    float rsum = 0.f;
    #pragma unroll
    for (int i = 0; i < 8; i++) {
        int k = t + i * 256;
        float E = __expf(Srow[k] - cmb[k]);
        float A = fmaf(E, alb[k], beb[k]);
        float ek = __expf(A);
        e[i] = ek;
        rsum += ek;
    }

    __shared__ float sred[256];
    sred[t] = rsum;
    __syncthreads();
    #pragma unroll
    for (int off = 128; off; off >>= 1) {
        if (t < off) sred[t] += sred[t + off];
        __syncthreads();
    }
    float inv = 1.0f / sred[0];
    #pragma unroll
    for (int i = 0; i < 8; i++)
        Wrow[t + i * 256] = e[i] * inv;
}

// ===========================================================================
// Kernel 6: O = W @ V + Q                  (NN, per batch 2048x768x2048)
// ===========================================================================
__global__ void __launch_bounds__(256)
gemm_O_kernel(const float* __restrict__ Wmat, const float* __restrict__ V,
              const float* __restrict__ Q, float* __restrict__ O) {
    __shared__ float As[BK][BM];
    __shared__ float Bs[BK][BN];

    const int b = blockIdx.z;
    const float* A  = Wmat + (size_t)b * Lsz * Lsz;
    const float* Bm = V    + (size_t)b * Lsz * Dsz;
    const float* Qb = Q    + (size_t)b * Lsz * Dsz;
    float* C = O + (size_t)b * Lsz * Dsz;
    const int lda = Lsz, ldb = Dsz, ldc = Dsz;

    const int tid = threadIdx.x;
    const int tx = tid & 15, ty = tid >> 4;
    const int m0 = blockIdx.y * BM;
    const int n0 = blockIdx.x * BN;

    int aRow[2], aC4[2], bKr[2], bC4[2];
    #pragma unroll
    for (int t = 0; t < 2; t++) {
        int i = tid + t * 256;
        aRow[t] = i >> 2;  aC4[t] = (i & 3) * 4;
        bKr[t]  = i >> 5;  bC4[t] = (i & 31) * 4;
    }

    float acc[TM][TN];
    #pragma unroll
    for (int i = 0; i < TM; i++)
        #pragma unroll
        for (int j = 0; j < TN; j++) acc[i][j] = 0.f;

    float4 pa[2], pb[2];
    #pragma unroll
    for (int t = 0; t < 2; t++) {
        pa[t] = *reinterpret_cast<const float4*>(&A [(size_t)(m0 + aRow[t]) * lda + aC4[t]]);
        pb[t] = *reinterpret_cast<const float4*>(&Bm[(size_t)bKr[t] * ldb + n0 + bC4[t]]);
    }

    for (int k0 = 0; k0 < Lsz; k0 += BK) {
        #pragma unroll
        for (int t = 0; t < 2; t++) {
            As[aC4[t] + 0][aRow[t]] = pa[t].x; As[aC4[t] + 1][aRow[t]] = pa[t].y;
            As[aC4[t] + 2][aRow[t]] = pa[t].z; As[aC4[t] + 3][aRow[t]] = pa[t].w;
            *reinterpret_cast<float4*>(&Bs[bKr[t]][bC4[t]]) = pb[t];
        }
        __syncthreads();

        if (k0 + BK < Lsz) {
            #pragma unroll
            for (int t = 0; t < 2; t++) {
                pa[t] = *reinterpret_cast<const float4*>(
                    &A [(size_t)(m0 + aRow[t]) * lda + (k0 + BK) + aC4[t]]);
                pb[t] = *reinterpret_cast<const float4*>(
                    &Bm[(size_t)(k0 + BK + bKr[t]) * ldb + n0 + bC4[t]]);
            }
        }

        #pragma unroll
        for (int k = 0; k < BK; k++) {
            float a[TM], bb[TN];
            #pragma unroll
            for (int i = 0; i < TM; i++) a[i] = As[k][ty * TM + i];
            #pragma unroll
            for (int j = 0; j < TN; j++) bb[j] = Bs[k][tx * TN + j];
            #pragma unroll
            for (int i = 0; i < TM; i++)
                #pragma unroll
                for (int j = 0; j < TN; j++) acc[i][j] = fmaf(a[i], bb[j], acc[i][j]);
        }
        __syncthreads();
    }

    #pragma unroll
    for (int i = 0; i < TM; i++) {
        int m = m0 + ty * TM + i;
        #pragma unroll
        for (int j = 0; j < TN; j += 4) {
            int n = n0 + tx * TN + j;
            float4 qv = *reinterpret_cast<const float4*>(&Qb[(size_t)m * ldc + n]);
            float4 v4;
            v4.x = acc[i][j + 0] + qv.x;
            v4.y = acc[i][j + 1] + qv.y;
            v4.z = acc[i][j + 2] + qv.z;
            v4.w = acc[i][j + 3] + qv.w;
            *reinterpret_cast<float4*>(&C[(size_t)m * ldc + n]) = v4;
        }
    }
}

// ===========================================================================
// Launch
// ===========================================================================
extern "C" void kernel_launch(void* const* d_in, const int* in_sizes, int n_in,
                              void* d_out, int out_size) {
    const float* q  = (const float*)d_in[0];
    const float* k  = (const float*)d_in[1];
    const float* v  = (const float*)d_in[2];
    const float* W1 = (const float*)d_in[3];
    const float* b1 = (const float*)d_in[4];
    const float* W2 = (const float*)d_in[5];
    const float* b2 = (const float*)d_in[6];

    float* out = (float*)d_out;
    float* Oout = out;                                        // [B, L, D]
    float* Wout = out + (size_t)Bsz * Lsz * Dsz;              // [B, L, L]

    // 1) hidden = tanh(V@W1+b1)
    gemm_h_kernel<<<dim3(Hsz / BN, (Bsz * Lsz) / BM), 256>>>(v, W1, b1);
    // 2) g = hidden @ W2 + b2
    reduce_g_kernel<<<(Bsz * Lsz) / 8, 256>>>(W2, b2);
    // 3) S = Q@K^T / sqrt(L)
    gemm_S_kernel<<<dim3(Lsz / BN, Lsz / BM, Bsz), 256>>>(q, k);
    // 4) column softmax stats + fused coefficients
    colstats_kernel<<<dim3(Lsz / 32, Bsz), dim3(32, 16)>>>();
    // 5) row transform + row softmax -> attn_weights (directly into d_out)
    rowpass_kernel<<<dim3(Lsz, Bsz), 256>>>(Wout);
    // 6) O = W@V + Q -> attn_output
    gemm_O_kernel<<<dim3(Dsz / BN, Lsz / BM, Bsz), 256>>>(Wout, v, q, Oout);
}

// round 3
// speedup vs baseline: 2.7038x; 2.7038x over previous
#include <cuda_runtime.h>
#include <cuda_bf16.h>
#include <math.h>
#include <stdint.h>

// Problem constants
#define Bsz 8
#define Lsz 2048
#define Dsz 768
#define Hsz 512

#define INV_SQRT_L 0.022097086912079608f   // 1/sqrt(2048)
#define INV_SQRT_D 0.036084391824351615f   // 1/sqrt(768)
#define INV_L      4.8828125e-4f           // 1/2048

// ---------------------------------------------------------------------------
// Scratch (static device globals; no allocation anywhere)
// ---------------------------------------------------------------------------
__device__ float d_S[(size_t)Bsz * Lsz * Lsz];      // 134 MB scores
__device__ float d_h[(size_t)Bsz * Lsz * Hsz];      // 32 MB hidden tanh(v@W1+b1)
__device__ float d_g[Bsz * Lsz];                    // gate
__device__ float d_cm[Bsz * Lsz];                   // column max
__device__ float d_alpha[Bsz * Lsz];                // (1-g)/(colsum*sqrt(D))
__device__ float d_beta[Bsz * Lsz];                 // g/(L*sqrt(D))

// ---------------------------------------------------------------------------
// TF32 tensor-core GEMM config: 128x128 block tile, BK=16, 256 threads
// 8 warps as 2(M) x 4(N): warp tile 64x32 -> 4x4 m16n8k8 mma per k8 step.
// smem stride padded to 136 => fragment loads are bank-conflict-free
// (bank = (8*tg + g) mod 32 covers all 32 banks).
// ---------------------------------------------------------------------------
#define BM 128
#define BN 128
#define BK 16
#define SMS (BM + 8)     // padded stride = 136
#define WM_T 4           // m16 tiles per warp
#define WN_T 4           // n8 tiles per warp

__device__ __forceinline__ uint32_t f2tf32(float f) {
    uint32_t r;
    asm("cvt.rna.tf32.f32 %0, %1;" : "=r"(r) : "f"(f));
    return r;
}

__device__ __forceinline__ void mma_tf32(float* c, const uint32_t* a, const uint32_t* b) {
    asm volatile(
        "mma.sync.aligned.m16n8k8.row.col.f32.tf32.tf32.f32 "
        "{%0,%1,%2,%3}, {%4,%5,%6,%7}, {%8,%9}, {%0,%1,%2,%3};"
        : "+f"(c[0]), "+f"(c[1]), "+f"(c[2]), "+f"(c[3])
        : "r"(a[0]), "r"(a[1]), "r"(a[2]), "r"(a[3]), "r"(b[0]), "r"(b[1]));
}

// Compute all 2 k-steps of one smem tile into acc.
__device__ __forceinline__ void mma_block(
    const uint32_t (*As)[SMS], const uint32_t (*Bs)[SMS],
    float acc[WM_T][WN_T][4], int wm0, int wn0, int g, int tg)
{
    #pragma unroll
    for (int kk = 0; kk < BK; kk += 8) {
        uint32_t af[WM_T][4], bf[WN_T][2];
        #pragma unroll
        for (int mi = 0; mi < WM_T; mi++) {
            int m = wm0 + mi * 16 + g;
            af[mi][0] = As[kk + tg][m];
            af[mi][1] = As[kk + tg][m + 8];
            af[mi][2] = As[kk + tg + 4][m];
            af[mi][3] = As[kk + tg + 4][m + 8];
        }
        #pragma unroll
        for (int ni = 0; ni < WN_T; ni++) {
            int n = wn0 + ni * 8 + g;
            bf[ni][0] = Bs[kk + tg][n];
            bf[ni][1] = Bs[kk + tg + 4][n];
        }
        #pragma unroll
        for (int mi = 0; mi < WM_T; mi++)
            #pragma unroll
            for (int ni = 0; ni < WN_T; ni++)
                mma_tf32(acc[mi][ni], af[mi], bf[ni]);
    }
}

// ===========================================================================
// Kernel 1: h = tanh(Vflat @ W1 + b1)      (NN, M=16384, N=512, K=768)
// ===========================================================================
__global__ void __launch_bounds__(256)
gemm_h_kernel(const float* __restrict__ V, const float* __restrict__ W1,
              const float* __restrict__ b1) {
    __shared__ uint32_t As[BK][SMS];
    __shared__ uint32_t Bs[BK][SMS];

    const int lda = Dsz, ldb = Hsz, ldc = Hsz;
    const int tid = threadIdx.x;
    const int warpId = tid >> 5, lane = tid & 31;
    const int g = lane >> 2, tg = lane & 3;
    const int wm0 = (warpId & 1) * 64, wn0 = (warpId >> 1) * 32;
    const int m0 = blockIdx.y * BM;
    const int n0 = blockIdx.x * BN;

    int aRow[2], aC4[2], bKr[2], bC4[2];
    #pragma unroll
    for (int t = 0; t < 2; t++) {
        int i = tid + t * 256;
        aRow[t] = i >> 2;  aC4[t] = (i & 3) * 4;
        bKr[t]  = i >> 5;  bC4[t] = (i & 31) * 4;
    }

    float acc[WM_T][WN_T][4];
    #pragma unroll
    for (int mi = 0; mi < WM_T; mi++)
        #pragma unroll
        for (int ni = 0; ni < WN_T; ni++)
            #pragma unroll
            for (int r = 0; r < 4; r++) acc[mi][ni][r] = 0.f;

    float4 pa[2], pb[2];
    #pragma unroll
    for (int t = 0; t < 2; t++) {
        pa[t] = *reinterpret_cast<const float4*>(&V [(size_t)(m0 + aRow[t]) * lda + aC4[t]]);
        pb[t] = *reinterpret_cast<const float4*>(&W1[(size_t)bKr[t] * ldb + n0 + bC4[t]]);
    }

    for (int k0 = 0; k0 < Dsz; k0 += BK) {
        #pragma unroll
        for (int t = 0; t < 2; t++) {
            As[aC4[t] + 0][aRow[t]] = f2tf32(pa[t].x);
            As[aC4[t] + 1][aRow[t]] = f2tf32(pa[t].y);
            As[aC4[t] + 2][aRow[t]] = f2tf32(pa[t].z);
            As[aC4[t] + 3][aRow[t]] = f2tf32(pa[t].w);
            Bs[bKr[t]][bC4[t] + 0] = f2tf32(pb[t].x);
            Bs[bKr[t]][bC4[t] + 1] = f2tf32(pb[t].y);
            Bs[bKr[t]][bC4[t] + 2] = f2tf32(pb[t].z);
            Bs[bKr[t]][bC4[t] + 3] = f2tf32(pb[t].w);
        }
        __syncthreads();

        if (k0 + BK < Dsz) {
            #pragma unroll
            for (int t = 0; t < 2; t++) {
                pa[t] = *reinterpret_cast<const float4*>(
                    &V [(size_t)(m0 + aRow[t]) * lda + (k0 + BK) + aC4[t]]);
                pb[t] = *reinterpret_cast<const float4*>(
                    &W1[(size_t)(k0 + BK + bKr[t]) * ldb + n0 + bC4[t]]);
            }
        }

        mma_block(As, Bs, acc, wm0, wn0, g, tg);
        __syncthreads();
    }

    #pragma unroll
    for (int mi = 0; mi < WM_T; mi++) {
        int m = m0 + wm0 + mi * 16 + g;
        #pragma unroll
        for (int ni = 0; ni < WN_T; ni++) {
            int n = n0 + wn0 + ni * 8 + 2 * tg;
            float2 v0, v1;
            v0.x = tanhf(acc[mi][ni][0] + b1[n + 0]);
            v0.y = tanhf(acc[mi][ni][1] + b1[n + 1]);
            v1.x = tanhf(acc[mi][ni][2] + b1[n + 0]);
            v1.y = tanhf(acc[mi][ni][3] + b1[n + 1]);
            *reinterpret_cast<float2*>(&d_h[(size_t)m * ldc + n]) = v0;
            *reinterpret_cast<float2*>(&d_h[(size_t)(m + 8) * ldc + n]) = v1;
        }
    }
}

// ===========================================================================
// Kernel 2: g[r] = h[r,:] . W2 + b2        (one warp per row)
// ===========================================================================
__global__ void __launch_bounds__(256)
reduce_g_kernel(const float* __restrict__ W2, const float* __restrict__ b2) {
    int warp = threadIdx.x >> 5, lane = threadIdx.x & 31;
    int row = blockIdx.x * 8 + warp;
    const float* hr = &d_h[(size_t)row * Hsz];
    float s = 0.f;
    #pragma unroll 4
    for (int i = lane; i < Hsz; i += 32) s = fmaf(hr[i], W2[i], s);
    #pragma unroll
    for (int off = 16; off; off >>= 1) s += __shfl_xor_sync(0xFFFFFFFFu, s, off);
    if (lane == 0) d_g[row] = s + b2[0];
}

// ===========================================================================
// Kernel 3: S = Q @ K^T * (1/sqrt(L))      (NT, per batch 2048x2048x768)
// ===========================================================================
__global__ void __launch_bounds__(256)
gemm_S_kernel(const float* __restrict__ Q, const float* __restrict__ Kmat) {
    __shared__ uint32_t As[BK][SMS];
    __shared__ uint32_t Bs[BK][SMS];

    const int b = blockIdx.z;
    const float* A  = Q    + (size_t)b * Lsz * Dsz;
    const float* Bm = Kmat + (size_t)b * Lsz * Dsz;
    float* C = &d_S[(size_t)b * Lsz * Lsz];
    const int lda = Dsz, ldb = Dsz, ldc = Lsz;

    const int tid = threadIdx.x;
    const int warpId = tid >> 5, lane = tid & 31;
    const int g = lane >> 2, tg = lane & 3;
    const int wm0 = (warpId & 1) * 64, wn0 = (warpId >> 1) * 32;
    const int m0 = blockIdx.y * BM;
    const int n0 = blockIdx.x * BN;

    int aRow[2], aC4[2];
    #pragma unroll
    for (int t = 0; t < 2; t++) {
        int i = tid + t * 256;
        aRow[t] = i >> 2; aC4[t] = (i & 3) * 4;
    }

    float acc[WM_T][WN_T][4];
    #pragma unroll
    for (int mi = 0; mi < WM_T; mi++)
        #pragma unroll
        for (int ni = 0; ni < WN_T; ni++)
            #pragma unroll
            for (int r = 0; r < 4; r++) acc[mi][ni][r] = 0.f;

    float4 pa[2], pb[2];
    #pragma unroll
    for (int t = 0; t < 2; t++) {
        pa[t] = *reinterpret_cast<const float4*>(&A [(size_t)(m0 + aRow[t]) * lda + aC4[t]]);
        pb[t] = *reinterpret_cast<const float4*>(&Bm[(size_t)(n0 + aRow[t]) * ldb + aC4[t]]);
    }

    for (int k0 = 0; k0 < Dsz; k0 += BK) {
        #pragma unroll
        for (int t = 0; t < 2; t++) {
            As[aC4[t] + 0][aRow[t]] = f2tf32(pa[t].x);
            As[aC4[t] + 1][aRow[t]] = f2tf32(pa[t].y);
            As[aC4[t] + 2][aRow[t]] = f2tf32(pa[t].z);
            As[aC4[t] + 3][aRow[t]] = f2tf32(pa[t].w);
            Bs[aC4[t] + 0][aRow[t]] = f2tf32(pb[t].x);
            Bs[aC4[t] + 1][aRow[t]] = f2tf32(pb[t].y);
            Bs[aC4[t] + 2][aRow[t]] = f2tf32(pb[t].z);
            Bs[aC4[t] + 3][aRow[t]] = f2tf32(pb[t].w);
        }
        __syncthreads();

        if (k0 + BK < Dsz) {
            #pragma unroll
            for (int t = 0; t < 2; t++) {
                pa[t] = *reinterpret_cast<const float4*>(
                    &A [(size_t)(m0 + aRow[t]) * lda + (k0 + BK) + aC4[t]]);
                pb[t] = *reinterpret_cast<const float4*>(
                    &Bm[(size_t)(n0 + aRow[t]) * ldb + (k0 + BK) + aC4[t]]);
            }
        }

        mma_block(As, Bs, acc, wm0, wn0, g, tg);
        __syncthreads();
    }

    #pragma unroll
    for (int mi = 0; mi < WM_T; mi++) {
        int m = m0 + wm0 + mi * 16 + g;
        #pragma unroll
        for (int ni = 0; ni < WN_T; ni++) {
            int n = n0 + wn0 + ni * 8 + 2 * tg;
            float2 v0, v1;
            v0.x = acc[mi][ni][0] * INV_SQRT_L;
            v0.y = acc[mi][ni][1] * INV_SQRT_L;
            v1.x = acc[mi][ni][2] * INV_SQRT_L;
            v1.y = acc[mi][ni][3] * INV_SQRT_L;
            *reinterpret_cast<float2*>(&C[(size_t)m * ldc + n]) = v0;
            *reinterpret_cast<float2*>(&C[(size_t)(m + 8) * ldc + n]) = v1;
        }
    }
}

// ===========================================================================
// Kernel 4: column stats (softmax over q axis) + per-k coefficients
// ===========================================================================
__global__ void __launch_bounds__(512)
colstats_kernel() {
    const int b = blockIdx.y;
    const int kx = threadIdx.x;                 // 0..31
    const int qy = threadIdx.y;                 // 0..15
    const int k = blockIdx.x * 32 + kx;
    const float* Sb = &d_S[(size_t)b * Lsz * Lsz];

    __shared__ float red[16][33];

    float m = -INFINITY;
    #pragma unroll 4
    for (int q = qy; q < Lsz; q += 16)
        m = fmaxf(m, Sb[(size_t)q * Lsz + k]);
    red[qy][kx] = m;
    __syncthreads();
    if (qy == 0) {
        float mm = red[0][kx];
        #pragma unroll
        for (int i = 1; i < 16; i++) mm = fmaxf(mm, red[i][kx]);
        red[0][kx] = mm;
    }
    __syncthreads();
    m = red[0][kx];
    __syncthreads();

    float s = 0.f;
    #pragma unroll 4
    for (int q = qy; q < Lsz; q += 16)
        s += __expf(Sb[(size_t)q * Lsz + k] - m);
    red[qy][kx] = s;
    __syncthreads();
    if (qy == 0) {
        float ss = red[0][kx];
        #pragma unroll
        for (int i = 1; i < 16; i++) ss += red[i][kx];
        float gk = d_g[b * Lsz + k];
        d_cm[b * Lsz + k]    = m;
        d_alpha[b * Lsz + k] = (1.0f - gk) * INV_SQRT_D / ss;
        d_beta[b * Lsz + k]  = gk * INV_L * INV_SQRT_D;
    }
}

// ===========================================================================
// Kernel 5: row pass — W[b,q,k] = softmax_k( exp(S-cm[k])*alpha[k]+beta[k] )
// ===========================================================================
__global__ void __launch_bounds__(256)
rowpass_kernel(float* __restrict__ Wout) {
    const int b = blockIdx.y;
    const int q = blockIdx.x;
    const float* Srow = &d_S[((size_t)b * Lsz + q) * Lsz];
    float* Wrow = Wout + ((size_t)b * Lsz + q) * Lsz;
    const float* cmb = &d_cm[b * Lsz];
    const float* alb = &d_alpha[b * Lsz];
    const float* beb = &d_beta[b * Lsz];
    const int t = threadIdx.x;

    float e[8];
    float rsum = 0.f;
    #pragma unroll
    for (int i = 0; i < 8; i++) {
        int k = t + i * 256;
        float E = __expf(Srow[k] - cmb[k]);
        float A = fmaf(E, alb[k], beb[k]);
        float ek = __expf(A);
        e[i] = ek;
        rsum += ek;
    }

    __shared__ float sred[256];
    sred[t] = rsum;
    __syncthreads();
    #pragma unroll
    for (int off = 128; off; off >>= 1) {
        if (t < off) sred[t] += sred[t + off];
        __syncthreads();
    }
    float inv = 1.0f / sred[0];
    #pragma unroll
    for (int i = 0; i < 8; i++)
        Wrow[t + i * 256] = e[i] * inv;
}

// ===========================================================================
// Kernel 6: O = W @ V + Q                  (NN, per batch 2048x768x2048)
// ===========================================================================
__global__ void __launch_bounds__(256)
gemm_O_kernel(const float* __restrict__ Wmat, const float* __restrict__ V,
              const float* __restrict__ Q, float* __restrict__ O) {
    __shared__ uint32_t As[BK][SMS];
    __shared__ uint32_t Bs[BK][SMS];

    const int b = blockIdx.z;
    const float* A  = Wmat + (size_t)b * Lsz * Lsz;
    const float* Bm = V    + (size_t)b * Lsz * Dsz;
    const float* Qb = Q    + (size_t)b * Lsz * Dsz;
    float* C = O + (size_t)b * Lsz * Dsz;
    const int lda = Lsz, ldb = Dsz, ldc = Dsz;

    const int tid = threadIdx.x;
    const int warpId = tid >> 5, lane = tid & 31;
    const int g = lane >> 2, tg = lane & 3;
    const int wm0 = (warpId & 1) * 64, wn0 = (warpId >> 1) * 32;
    const int m0 = blockIdx.y * BM;
    const int n0 = blockIdx.x * BN;

    int aRow[2], aC4[2], bKr[2], bC4[2];
    #pragma unroll
    for (int t = 0; t < 2; t++) {
        int i = tid + t * 256;
        aRow[t] = i >> 2;  aC4[t] = (i & 3) * 4;
        bKr[t]  = i >> 5;  bC4[t] = (i & 31) * 4;
    }

    float acc[WM_T][WN_T][4];
    #pragma unroll
    for (int mi = 0; mi < WM_T; mi++)
        #pragma unroll
        for (int ni = 0; ni < WN_T; ni++)
            #pragma unroll
            for (int r = 0; r < 4; r++) acc[mi][ni][r] = 0.f;

    float4 pa[2], pb[2];
    #pragma unroll
    for (int t = 0; t < 2; t++) {
        pa[t] = *reinterpret_cast<const float4*>(&A [(size_t)(m0 + aRow[t]) * lda + aC4[t]]);
        pb[t] = *reinterpret_cast<const float4*>(&Bm[(size_t)bKr[t] * ldb + n0 + bC4[t]]);
    }

    for (int k0 = 0; k0 < Lsz; k0 += BK) {
        #pragma unroll
        for (int t = 0; t < 2; t++) {
            As[aC4[t] + 0][aRow[t]] = f2tf32(pa[t].x);
            As[aC4[t] + 1][aRow[t]] = f2tf32(pa[t].y);
            As[aC4[t] + 2][aRow[t]] = f2tf32(pa[t].z);
            As[aC4[t] + 3][aRow[t]] = f2tf32(pa[t].w);
            Bs[bKr[t]][bC4[t] + 0] = f2tf32(pb[t].x);
            Bs[bKr[t]][bC4[t] + 1] = f2tf32(pb[t].y);
            Bs[bKr[t]][bC4[t] + 2] = f2tf32(pb[t].z);
            Bs[bKr[t]][bC4[t] + 3] = f2tf32(pb[t].w);
        }
        __syncthreads();

        if (k0 + BK < Lsz) {
            #pragma unroll
            for (int t = 0; t < 2; t++) {
                pa[t] = *reinterpret_cast<const float4*>(
                    &A [(size_t)(m0 + aRow[t]) * lda + (k0 + BK) + aC4[t]]);
                pb[t] = *reinterpret_cast<const float4*>(
                    &Bm[(size_t)(k0 + BK + bKr[t]) * ldb + n0 + bC4[t]]);
            }
        }

        mma_block(As, Bs, acc, wm0, wn0, g, tg);
        __syncthreads();
    }

    #pragma unroll
    for (int mi = 0; mi < WM_T; mi++) {
        int m = m0 + wm0 + mi * 16 + g;
        #pragma unroll
        for (int ni = 0; ni < WN_T; ni++) {
            int n = n0 + wn0 + ni * 8 + 2 * tg;
            float2 q0 = *reinterpret_cast<const float2*>(&Qb[(size_t)m * ldc + n]);
            float2 q1 = *reinterpret_cast<const float2*>(&Qb[(size_t)(m + 8) * ldc + n]);
            float2 v0, v1;
            v0.x = acc[mi][ni][0] + q0.x;
            v0.y = acc[mi][ni][1] + q0.y;
            v1.x = acc[mi][ni][2] + q1.x;
            v1.y = acc[mi][ni][3] + q1.y;
            *reinterpret_cast<float2*>(&C[(size_t)m * ldc + n]) = v0;
            *reinterpret_cast<float2*>(&C[(size_t)(m + 8) * ldc + n]) = v1;
        }
    }
}

// ===========================================================================
// Launch
// ===========================================================================
extern "C" void kernel_launch(void* const* d_in, const int* in_sizes, int n_in,
                              void* d_out, int out_size) {
    const float* q  = (const float*)d_in[0];
    const float* k  = (const float*)d_in[1];
    const float* v  = (const float*)d_in[2];
    const float* W1 = (const float*)d_in[3];
    const float* b1 = (const float*)d_in[4];
    const float* W2 = (const float*)d_in[5];
    const float* b2 = (const float*)d_in[6];

    float* out = (float*)d_out;
    float* Oout = out;                                        // [B, L, D]
    float* Wout = out + (size_t)Bsz * Lsz * Dsz;              // [B, L, L]

    // 1) hidden = tanh(V@W1+b1)
    gemm_h_kernel<<<dim3(Hsz / BN, (Bsz * Lsz) / BM), 256>>>(v, W1, b1);
    // 2) g = hidden @ W2 + b2
    reduce_g_kernel<<<(Bsz * Lsz) / 8, 256>>>(W2, b2);
    // 3) S = Q@K^T / sqrt(L)
    gemm_S_kernel<<<dim3(Lsz / BN, Lsz / BM, Bsz), 256>>>(q, k);
    // 4) column softmax stats + fused coefficients
    colstats_kernel<<<dim3(Lsz / 32, Bsz), dim3(32, 16)>>>();
    // 5) row transform + row softmax -> attn_weights (directly into d_out)
    rowpass_kernel<<<dim3(Lsz, Bsz), 256>>>(Wout);
    // 6) O = W@V + Q -> attn_output
    gemm_O_kernel<<<dim3(Dsz / BN, Lsz / BM, Bsz), 256>>>(Wout, v, q, Oout);
}